// round 11
// baseline (speedup 1.0000x reference)
#include <cuda_runtime.h>
#include <math.h>

// Problem constants
constexpr int BB = 64;     // batch
constexpr int SS = 2048;   // seq len
constexpr int II = 256;    // input dim
constexpr int HH = 512;    // hidden dim
constexpr int GG = 1536;   // 3*H

// ---------------- device scratch (no allocations allowed) ----------------
__device__ float g_xproj[(size_t)BB * SS * GG];  // precomputed input projections
__device__ float g_h[4 * BB * HH];               // 4-deep h ring (zero-init; restored at end)
__device__ unsigned g_flag[128];                 // [mg*32+ng] = latest step+1 published (reset at end)
__device__ unsigned g_gcnt[4];                   // per-group arrival counters (self-resetting)
__device__ unsigned g_ggen[4];                   // per-group monotonic generation

// ---------------- acquire/release helpers ----------------
__device__ __forceinline__ unsigned ld_acq(const unsigned* p) {
    unsigned v;
    asm volatile("ld.acquire.gpu.global.u32 %0, [%1];" : "=r"(v) : "l"(p) : "memory");
    return v;
}
__device__ __forceinline__ void st_rel(unsigned* p, unsigned v) {
    asm volatile("st.release.gpu.global.u32 [%0], %1;" :: "l"(p), "r"(v) : "memory");
}
__device__ __forceinline__ void named_bar(int id, int cnt) {
    asm volatile("bar.sync %0, %1;" :: "r"(id), "r"(cnt) : "memory");
}

// ---------------- f32x2 helpers (FFMA2 — only reachable via PTX) ----------------
__device__ __forceinline__ void ffma2(unsigned long long& d,
                                      unsigned long long a,
                                      unsigned long long b) {
    asm("fma.rn.f32x2 %0, %1, %2, %0;" : "+l"(d) : "l"(a), "l"(b));
}
__device__ __forceinline__ unsigned long long dup2(float x) {
    unsigned long long r;
    asm("mov.b64 %0, {%1, %1};" : "=l"(r) : "f"(x));
    return r;
}
__device__ __forceinline__ float2 unpack2(unsigned long long v) {
    float2 f;
    asm("mov.b64 {%0, %1}, %2;" : "=f"(f.x), "=f"(f.y) : "l"(v));
    return f;
}

// Fast, NaN-safe sigmoid/tanh (MUFU-based; error << 1e-3 tolerance)
__device__ __forceinline__ float fsigmoid(float z) {
    return __fdividef(1.f, 1.f + __expf(-z));
}
__device__ __forceinline__ float ftanh(float x) {
    return fmaf(2.f, fsigmoid(2.f * x), -1.f);
}

// ---------------- Phase 1: x_proj = x @ W + bias ----------------
// (unchanged — known good, ~1.7 ms)
__global__ __launch_bounds__(256) void gemm_xw(const float* __restrict__ A,
                                               const float* __restrict__ Bm,
                                               const float* __restrict__ bias) {
    __shared__ float As[16 * 132];
    __shared__ float Bs[16 * 132];
    const int tid = threadIdx.x;
    const int bx = blockIdx.x;
    const int by = blockIdx.y;
    const int tr = tid >> 4, tc = tid & 15;
    const int rowA0 = by * 128;
    const int colB0 = bx * 128;
    const int iA_r = tid >> 2;
    const int iA_c = (tid & 3) * 4;
    const int iB_r = tid >> 5;
    const int iB_c = (tid & 31) * 4;

    unsigned long long acc2[8][4];
#pragma unroll
    for (int i = 0; i < 8; i++)
#pragma unroll
        for (int j = 0; j < 4; j++) acc2[i][j] = 0ull;

    for (int kt = 0; kt < II; kt += 16) {
#pragma unroll
        for (int off = 0; off < 128; off += 64) {
            float4 v = *(const float4*)&A[(size_t)(rowA0 + iA_r + off) * II + kt + iA_c];
            As[(iA_c + 0) * 132 + iA_r + off] = v.x;
            As[(iA_c + 1) * 132 + iA_r + off] = v.y;
            As[(iA_c + 2) * 132 + iA_r + off] = v.z;
            As[(iA_c + 3) * 132 + iA_r + off] = v.w;
        }
#pragma unroll
        for (int off = 0; off < 16; off += 8) {
            float4 v = *(const float4*)&Bm[(size_t)(kt + iB_r + off) * GG + colB0 + iB_c];
            *(float4*)&Bs[(iB_r + off) * 132 + iB_c] = v;
        }
        __syncthreads();
#pragma unroll
        for (int k = 0; k < 16; k++) {
            float rm[8];
            *(float4*)&rm[0] = *(const float4*)&As[k * 132 + tr * 8];
            *(float4*)&rm[4] = *(const float4*)&As[k * 132 + tr * 8 + 4];
            unsigned long long bb[4];
#pragma unroll
            for (int jp = 0; jp < 4; jp++)
                bb[jp] = *(const unsigned long long*)&Bs[k * 132 + 32 * jp + 2 * tc];
#pragma unroll
            for (int i = 0; i < 8; i++) {
                unsigned long long a = dup2(rm[i]);
#pragma unroll
                for (int j = 0; j < 4; j++) ffma2(acc2[i][j], a, bb[j]);
            }
        }
        __syncthreads();
    }
#pragma unroll
    for (int i = 0; i < 8; i++) {
        int row = rowA0 + tr * 8 + i;
#pragma unroll
        for (int jp = 0; jp < 4; jp++) {
            int col = colB0 + 32 * jp + 2 * tc;
            float2 bv = *(const float2*)&bias[col];
            float2 p = unpack2(acc2[i][jp]);
            float2 o;
            o.x = p.x + bv.x;
            o.y = p.y + bv.y;
            *(float2*)&g_xproj[(size_t)row * GG + col] = o;
        }
    }
}

// ---------------- per-group grid barrier (skew bound only; every 3rd step) ----------------
__device__ __forceinline__ void groupbar(int mg, unsigned nctas) {
    __syncthreads();
    if (threadIdx.x == 0) {
        __threadfence();
        unsigned gen = ld_acq(&g_ggen[mg]);
        if (atomicAdd(&g_gcnt[mg], 1u) == nctas - 1) {
            g_gcnt[mg] = 0;
            st_rel(&g_ggen[mg], gen + 1);
        } else {
            while (ld_acq(&g_ggen[mg]) == gen) { }
        }
    }
    __syncthreads();
}

// ---------------- Phase 2: persistent recurrence kernel ----------------
// 128 CTAs = 4 batch-groups(16 rows) x 32 feature-groups(16 features).
// 16 warps = 8 k-chunks(64) x 2 col-halves(24 cols). Per-warp dataflow:
// spin on 2 producer flags -> load own 16x32 h slice -> pair-barrier -> matmul.
// No per-step grid barrier; 4-deep h ring + groupbar every 3 steps bounds skew.
constexpr int NT = 512;
constexpr int PU = 1036;                 // U2 pitch (conflict-free, proven round 9/10)
constexpr int PHK = 68;                  // h region row pitch (4r banks, conflict-free)
constexpr int SM_U2 = 24 * PU;           // 24864
constexpr int SM_HK = 8 * 16 * PHK;      // 8704 (8 k-chunk regions of 16x64)
constexpr int RED1 = 16 * 672;           // 10752 per buffer (per-warp 24 cols x pitch 28)
constexpr int SMEM_BYTES = (SM_U2 + SM_HK + 2 * RED1) * 4;  // 220,288 B

__global__ __launch_bounds__(NT, 1) void lstm_rec(const float* __restrict__ U,
                                                  float* __restrict__ out) {
    extern __shared__ float sm[];
    float* U2_s = sm;                     // [jp][2k+{0,1}]
    float* h_k  = sm + SM_U2;             // [kq][r][PHK]
    float* red0 = sm + SM_U2 + SM_HK;     // double-buffered partials

    const int tid = threadIdx.x;
    const int bid = blockIdx.x;
    const int mg = bid >> 5;              // batch group 0..3
    const int ng = bid & 31;              // feature group 0..31
    const int r0 = mg * 16;
    const int n16 = ng * 16;

    // Load U slice pair-interleaved (same as round 10)
    for (int idx = tid; idx < 24 * 512; idx += NT) {
        int jp = idx % 24;
        int k = idx / 24;
        int c0 = 2 * jp, c1 = 2 * jp + 1;
        int colg0 = (c0 >> 4) * HH + n16 + (c0 & 15);
        int colg1 = (c1 >> 4) * HH + n16 + (c1 & 15);
        U2_s[jp * PU + 2 * k]     = U[(size_t)k * GG + colg0];
        U2_s[jp * PU + 2 * k + 1] = U[(size_t)k * GG + colg1];
    }

    const int lane = tid & 31, w = tid >> 5;
    const int kq = w & 7;                 // k-chunk: k in [kq*64, kq*64+64)
    const int ch = w >> 3;                // col half: pairs 12*ch .. 12*ch+11
    const int rgi = lane & 7;             // rows rgi, rgi+8
    const int cgi = lane >> 3;            // local pairs 3*cgi .. 3*cgi+2
    float* hreg = h_k + kq * (16 * PHK);

    // h loader mapping: lane -> (row, 16-feature half of this warp's 32-feature slice)
    const int ldr = lane >> 1;            // 0..15
    const int ldh = lane & 1;             // 0..1
    const int f0 = kq * 64 + ch * 32;     // this warp loads features f0 .. f0+31

    // Elementwise mapping: threads 0..255 own (er, ef)
    const int er = tid >> 4, ef = tid & 15;   // valid when tid < 256
    const bool do_elem = (tid < 256);

    float* outh = out + (size_t)BB * SS * HH;
    float* outc = outh + BB * HH;
    unsigned* myflag = &g_flag[mg * 32 + ng];

    __syncthreads();  // U2_s ready

    for (int t = 0; t < SS; ++t) {
        float* redw = red0 + (t & 1) * RED1;

        // xp prefetch first (DRAM latency hidden behind spin + h load + matmul)
        float xp[3];
        if (do_elem) {
#pragma unroll
            for (int g = 0; g < 3; g++)
                xp[g] = __ldg(&g_xproj[((size_t)(r0 + er) * SS + t) * GG + g * HH + n16 + ef]);
        }

        // Wait only for this warp's 2 producer CTAs, then load own h slice
        if (t > 0 && lane < 2) {
            const unsigned* pf = &g_flag[mg * 32 + (f0 >> 4) + lane];
            while (ld_acq(pf) < (unsigned)t) { }
        }
        __syncwarp();

        const float* hbuf = g_h + (size_t)(t & 3) * (BB * HH);
        {
            const float* src = &hbuf[(r0 + ldr) * HH + f0 + ldh * 16];
            float* dst = &hreg[ldr * PHK + ch * 32 + ldh * 16];
#pragma unroll
            for (int q = 0; q < 4; q++) {
                float4 v = __ldcg((const float4*)(src + 4 * q));
                *(float4*)(dst + 4 * q) = v;
            }
        }
        named_bar(1 + kq, 64);            // pair (kq, ch=0) with (kq, ch=1)

        // matmul: 16 rows x 24 cols x 64 k -> acc2[2 rows][3 pairs]
        unsigned long long acc2[2][3];
#pragma unroll
        for (int i = 0; i < 2; i++)
#pragma unroll
            for (int j = 0; j < 3; j++) acc2[i][j] = 0ull;

        const int kg0 = kq * 64;          // global k base for U addressing
#pragma unroll 4
        for (int kl = 0; kl < 64; kl += 2) {
            float2 h0 = *(const float2*)&hreg[rgi * PHK + kl];
            float2 h1 = *(const float2*)&hreg[(rgi + 8) * PHK + kl];
            unsigned long long a00 = dup2(h0.x), a01 = dup2(h0.y);
            unsigned long long a10 = dup2(h1.x), a11 = dup2(h1.y);
#pragma unroll
            for (int jj = 0; jj < 3; jj++) {
                ulonglong2 ub = *(const ulonglong2*)&U2_s[(12 * ch + 3 * cgi + jj) * PU + 2 * (kg0 + kl)];
                ffma2(acc2[0][jj], a00, ub.x);
                ffma2(acc2[0][jj], a01, ub.y);
                ffma2(acc2[1][jj], a10, ub.x);
                ffma2(acc2[1][jj], a11, ub.y);
            }
        }

        // store partials: col-major pitch 28 (STS.32, conflict-free: banks 8cgi+rgi)
#pragma unroll
        for (int i = 0; i < 2; i++) {
            int r = rgi + 8 * i;
#pragma unroll
            for (int jj = 0; jj < 3; jj++) {
                float2 fv = unpack2(acc2[i][jj]);
                int cl = (3 * cgi + jj) * 2;
                redw[w * 672 + cl * 28 + r] = fv.x;
                redw[w * 672 + (cl + 1) * 28 + r] = fv.y;
            }
        }
        __syncthreads();   // all partials of step t in redw

        // fused 8-way k-reduce + elementwise (threads 0..255)
        if (do_elem) {
            float gate[3];
#pragma unroll
            for (int g = 0; g < 3; g++) {
                int c = g * 16 + ef;
                int chc = (c >= 24);
                int base = (c - 24 * chc) * 28 + er + (chc ? 8 * 672 : 0);
                float v = xp[g];
#pragma unroll
                for (int q = 0; q < 8; q++) v += redw[base + q * 672];
                gate[g] = v;
            }
            float iv = fsigmoid(gate[0]);
            float gv = ftanh(gate[1]);
            float ov = fsigmoid(gate[2]);
            float cv = iv * gv;                  // no-forget: c = i*g
            float hv = ov * ftanh(cv);
            int b = r0 + er, jg = n16 + ef;
            if (t < SS - 1) {
                __stcg(&g_h[(size_t)((t + 1) & 3) * (BB * HH) + b * HH + jg], hv);
            } else {
                g_h[(size_t)b * HH + jg] = 0.f;  // restore h ring buf0 for next replay
                outh[b * HH + jg] = hv;          // h_f
                outc[b * HH + jg] = cv;          // c_f
            }
            out[((size_t)b * SS + t) * HH + jg] = hv;   // hidden_seq

            named_bar(9, 256);                   // elem warps done writing h chunk
            if (tid == 0 && t < SS - 1) {
                __threadfence();
                st_rel(myflag, (unsigned)(t + 1));  // publish h(t+1)
            }
        }

        // skew bound: 4-deep ring tolerates skew<4; barrier every 3 steps
        if ((t % 3 == 2) && t < SS - 1) groupbar(mg, 32);
    }

    // replay hygiene: everyone past their last waits, then reset flags
    groupbar(mg, 32);
    if (tid == 0) *myflag = 0u;
}

// ---------------- launch ----------------
extern "C" void kernel_launch(void* const* d_in, const int* in_sizes, int n_in,
                              void* d_out, int out_size) {
    const float* x    = (const float*)d_in[0];
    const float* W    = (const float*)d_in[1];
    const float* U    = (const float*)d_in[2];
    const float* bias = (const float*)d_in[3];
    float* out = (float*)d_out;

    cudaFuncSetAttribute(lstm_rec, cudaFuncAttributeMaxDynamicSharedMemorySize, SMEM_BYTES);

    dim3 g1(GG / 128, (BB * SS) / 128);   // 12 x 1024
    gemm_xw<<<g1, 256>>>(x, W, bias);
    lstm_rec<<<128, NT, SMEM_BYTES>>>(U, out);
}

// round 12
// speedup vs baseline: 1.1807x; 1.1807x over previous
#include <cuda_runtime.h>
#include <math.h>

// Problem constants
constexpr int BB = 64;     // batch
constexpr int SS = 2048;   // seq len
constexpr int II = 256;    // input dim
constexpr int HH = 512;    // hidden dim
constexpr int GG = 1536;   // 3*H

// ---------------- device scratch (no allocations allowed) ----------------
__device__ float g_xproj[(size_t)BB * SS * GG];  // precomputed input projections
__device__ float g_hA[BB * HH];                  // h ping (zero-init; restored at end)
__device__ float g_hB[BB * HH];                  // h pong

// ---------------- f32x2 helpers (FFMA2 — only reachable via PTX) ----------------
__device__ __forceinline__ void ffma2(unsigned long long& d,
                                      unsigned long long a,
                                      unsigned long long b) {
    asm("fma.rn.f32x2 %0, %1, %2, %0;" : "+l"(d) : "l"(a), "l"(b));
}
__device__ __forceinline__ unsigned long long dup2(float x) {
    unsigned long long r;
    asm("mov.b64 %0, {%1, %1};" : "=l"(r) : "f"(x));
    return r;
}
__device__ __forceinline__ float2 unpack2(unsigned long long v) {
    float2 f;
    asm("mov.b64 {%0, %1}, %2;" : "=f"(f.x), "=f"(f.y) : "l"(v));
    return f;
}

// Fast, NaN-safe sigmoid/tanh (MUFU-based; error << 1e-3 tolerance)
__device__ __forceinline__ float fsigmoid(float z) {
    return __fdividef(1.f, 1.f + __expf(-z));
}
__device__ __forceinline__ float ftanh(float x) {
    return fmaf(2.f, fsigmoid(2.f * x), -1.f);
}

// Cluster barrier halves (arrive = release, wait = acquire; cluster scope)
__device__ __forceinline__ void cluster_arrive() {
    asm volatile("barrier.cluster.arrive.aligned;" ::: "memory");
}
__device__ __forceinline__ void cluster_wait() {
    asm volatile("barrier.cluster.wait.aligned;" ::: "memory");
}

// ---------------- Phase 1: x_proj = x @ W + bias ----------------
// (unchanged — known good)
__global__ __launch_bounds__(256) void gemm_xw(const float* __restrict__ A,
                                               const float* __restrict__ Bm,
                                               const float* __restrict__ bias) {
    __shared__ float As[16 * 132];
    __shared__ float Bs[16 * 132];
    const int tid = threadIdx.x;
    const int bx = blockIdx.x;
    const int by = blockIdx.y;
    const int tr = tid >> 4, tc = tid & 15;
    const int rowA0 = by * 128;
    const int colB0 = bx * 128;
    const int iA_r = tid >> 2;
    const int iA_c = (tid & 3) * 4;
    const int iB_r = tid >> 5;
    const int iB_c = (tid & 31) * 4;

    unsigned long long acc2[8][4];
#pragma unroll
    for (int i = 0; i < 8; i++)
#pragma unroll
        for (int j = 0; j < 4; j++) acc2[i][j] = 0ull;

    for (int kt = 0; kt < II; kt += 16) {
#pragma unroll
        for (int off = 0; off < 128; off += 64) {
            float4 v = *(const float4*)&A[(size_t)(rowA0 + iA_r + off) * II + kt + iA_c];
            As[(iA_c + 0) * 132 + iA_r + off] = v.x;
            As[(iA_c + 1) * 132 + iA_r + off] = v.y;
            As[(iA_c + 2) * 132 + iA_r + off] = v.z;
            As[(iA_c + 3) * 132 + iA_r + off] = v.w;
        }
#pragma unroll
        for (int off = 0; off < 16; off += 8) {
            float4 v = *(const float4*)&Bm[(size_t)(kt + iB_r + off) * GG + colB0 + iB_c];
            *(float4*)&Bs[(iB_r + off) * 132 + iB_c] = v;
        }
        __syncthreads();
#pragma unroll
        for (int k = 0; k < 16; k++) {
            float rm[8];
            *(float4*)&rm[0] = *(const float4*)&As[k * 132 + tr * 8];
            *(float4*)&rm[4] = *(const float4*)&As[k * 132 + tr * 8 + 4];
            unsigned long long bb[4];
#pragma unroll
            for (int jp = 0; jp < 4; jp++)
                bb[jp] = *(const unsigned long long*)&Bs[k * 132 + 32 * jp + 2 * tc];
#pragma unroll
            for (int i = 0; i < 8; i++) {
                unsigned long long a = dup2(rm[i]);
#pragma unroll
                for (int j = 0; j < 4; j++) ffma2(acc2[i][j], a, bb[j]);
            }
        }
        __syncthreads();
    }
#pragma unroll
    for (int i = 0; i < 8; i++) {
        int row = rowA0 + tr * 8 + i;
#pragma unroll
        for (int jp = 0; jp < 4; jp++) {
            int col = colB0 + 32 * jp + 2 * tc;
            float2 bv = *(const float2*)&bias[col];
            float2 p = unpack2(acc2[i][jp]);
            float2 o;
            o.x = p.x + bv.x;
            o.y = p.y + bv.y;
            *(float2*)&g_xproj[(size_t)row * GG + col] = o;
        }
    }
}

// ---------------- Phase 2: cluster-synchronized recurrence ----------------
// 8 clusters of 16 CTAs. Cluster g owns batch rows 8g..8g+8; CTA rank c owns
// 32 features (96 gate cols), full U slice resident in smem (198KB).
// Per step: hw cluster barrier -> reload 8x512 h from L2 -> 8-warp matmul
// (k-split 4 x col-split 2, FFMA2) -> in-CTA reduce -> elem -> publish h.
constexpr int PU2 = 1032;            // U2 pair pitch: cgi quad offsets {0,2,4,6} mod 8
constexpr int PH2 = 516;             // h row pitch: rgi bank-pairs 2*rgi mod 16
constexpr int RP  = 10;              // red col pitch: STS banks {0,24,16,8}+rgi
constexpr int SM_U2 = 48 * PU2;      // 49,536 floats
constexpr int SM_H  = 8 * PH2;       // 4,128 floats
constexpr int SM_RED = 8 * 48 * RP;  // 3,840 floats (8 warps x 48 cols x RP)
constexpr int SMEM_BYTES = (SM_U2 + SM_H + SM_RED) * 4;  // 230,016 B

__global__ __launch_bounds__(256, 1) void lstm_rec(const float* __restrict__ U,
                                                   float* __restrict__ out) {
    extern __shared__ float sm[];
    float* U2_s = sm;                    // [pair p][2k+par], pitch PU2
    float* h_s  = sm + SM_U2;            // [r][k], pitch PH2
    float* red  = sm + SM_U2 + SM_H;     // [w][cl][r], cl pitch RP

    const int tid = threadIdx.x;
    const int bid = blockIdx.x;
    const int g = bid >> 4;              // cluster / batch group 0..7
    const int crank = bid & 15;          // rank in cluster
    const int r0 = g * 8;                // batch row base
    const int fbase = crank * 32;        // feature base

    // Load U slice: local col c = gate*32 + f -> global col = gate*512 + fbase + f
    // pair p = c>>1, parity = c&1
    for (int idx = tid; idx < 96 * 512; idx += 256) {
        int c = idx % 96;
        int k = idx / 96;
        int colg = (c >> 5) * HH + fbase + (c & 31);
        int p = c >> 1, par = c & 1;
        U2_s[p * PU2 + 2 * k + par] = U[(size_t)k * GG + colg];
    }

    const int lane = tid & 31, w = tid >> 5;  // 8 warps
    const int kq = w & 3;                // k chunk: [128*kq, 128*kq+128)
    const int cw = w >> 2;               // col half
    const int rgi = lane & 7;            // row (1 of 8)
    const int cgi = lane >> 3;           // 0..3
    const int pbase = 4 * cw + cgi;      // lane owns pairs pbase + 8*jj, jj=0..5
    const int kbase = kq * 128;

    // Elementwise mapping: thread (er=w, ef=lane) owns (row er, feature ef)... 
    const int er = tid >> 5;             // 0..7 (= w)
    const int ef = tid & 31;             // 0..31

    float* outh = out + (size_t)BB * SS * HH;
    float* outc = outh + BB * HH;

    __syncthreads();  // U2_s ready (cluster barrier not needed: t=0 reads zeros)

    for (int t = 0; t < SS; ++t) {
        if (t > 0) cluster_wait();       // acquire: peers' h(t) stores visible

        const float* hprev = (t & 1) ? g_hB : g_hA;
        float* hnext = (t & 1) ? g_hA : g_hB;

        // xp prefetch (DRAM latency hidden behind h load + matmul)
        float xp[3];
#pragma unroll
        for (int gg2 = 0; gg2 < 3; gg2++)
            xp[gg2] = __ldg(&g_xproj[((size_t)(r0 + er) * SS + t) * GG + gg2 * HH + fbase + ef]);

        // Load h slice (8x512) from global into smem (.cg: L1 incoherent)
        if (t == 0) {
            for (int q = tid; q < SM_H; q += 256) h_s[q] = 0.f;
        } else {
#pragma unroll
            for (int it = 0; it < 4; it++) {
                int q = tid + it * 256;          // 0..1023 float4s
                int r = q >> 7, c4 = q & 127;
                float4 v = __ldcg((const float4*)&hprev[(r0 + r) * HH + 4 * c4]);
                *(float4*)&h_s[r * PH2 + 4 * c4] = v;
            }
        }
        __syncthreads();

        // matmul: lane = 1 row x 6 pairs over 128 k
        unsigned long long acc2[6];
#pragma unroll
        for (int j = 0; j < 6; j++) acc2[j] = 0ull;

        const float* hp = &h_s[rgi * PH2 + kbase];
        const float* up = &U2_s[pbase * PU2 + 2 * kbase];
#pragma unroll 8
        for (int i = 0; i < 64; i++) {
            float2 h2 = *(const float2*)(hp + 2 * i);
            unsigned long long a0 = dup2(h2.x), a1 = dup2(h2.y);
#pragma unroll
            for (int jj = 0; jj < 6; jj++) {
                ulonglong2 ub = *(const ulonglong2*)(up + jj * (8 * PU2) + 4 * i);
                ffma2(acc2[jj], a0, ub.x);
                ffma2(acc2[jj], a1, ub.y);
            }
        }

        // store partials: cl = cgi*12 + jj*2 + parity, addr = w*480 + cl*RP + rgi
#pragma unroll
        for (int jj = 0; jj < 6; jj++) {
            float2 fv = unpack2(acc2[jj]);
            int cl = cgi * 12 + jj * 2;
            red[w * (48 * RP) + cl * RP + rgi] = fv.x;
            red[w * (48 * RP) + (cl + 1) * RP + rgi] = fv.y;
        }
        __syncthreads();

        // fused 4-way k-reduce + elementwise (all 256 threads: row er, feature ef)
        {
            float gate[3];
#pragma unroll
            for (int gg2 = 0; gg2 < 3; gg2++) {
                int c = gg2 * 32 + ef;
                int p = c >> 1, par = c & 1;
                int cl = (p & 3) * 12 + (p >> 3) * 2 + par;
                int wb = ((p >> 2) & 1) * 4;
                float v = xp[gg2];
#pragma unroll
                for (int q = 0; q < 4; q++)
                    v += red[(wb + q) * (48 * RP) + cl * RP + er];
                gate[gg2] = v;
            }
            float iv = fsigmoid(gate[0]);
            float gv = ftanh(gate[1]);
            float ov = fsigmoid(gate[2]);
            float cv = iv * gv;                  // no-forget: c = i*g
            float hv = ov * ftanh(cv);
            int b = r0 + er, jg = fbase + ef;

            if (t < SS - 1) {
                __stcg(&hnext[b * HH + jg], hv);   // publish h(t+1)
            } else {
                g_hA[b * HH + jg] = 0.f;           // restore ping buffer for replay
                outh[b * HH + jg] = hv;            // h_f
                outc[b * HH + jg] = cv;            // c_f
            }
            if (t < SS - 1) cluster_arrive();      // release: h(t+1) visible at wait
            out[((size_t)b * SS + t) * HH + jg] = hv;  // hidden_seq (off critical path)
        }
    }
}

// ---------------- launch ----------------
extern "C" void kernel_launch(void* const* d_in, const int* in_sizes, int n_in,
                              void* d_out, int out_size) {
    const float* x    = (const float*)d_in[0];
    const float* W    = (const float*)d_in[1];
    const float* U    = (const float*)d_in[2];
    const float* bias = (const float*)d_in[3];
    float* out = (float*)d_out;

    cudaFuncSetAttribute(lstm_rec, cudaFuncAttributeMaxDynamicSharedMemorySize, SMEM_BYTES);
    cudaFuncSetAttribute(lstm_rec, cudaFuncAttributeNonPortableClusterSizeAllowed, 1);

    dim3 g1(GG / 128, (BB * SS) / 128);   // 12 x 1024
    gemm_xw<<<g1, 256>>>(x, W, bias);

    cudaLaunchConfig_t cfg = {};
    cfg.gridDim = dim3(128, 1, 1);
    cfg.blockDim = dim3(256, 1, 1);
    cfg.dynamicSmemBytes = SMEM_BYTES;
    cfg.stream = 0;
    cudaLaunchAttribute attrs[1];
    attrs[0].id = cudaLaunchAttributeClusterDimension;
    attrs[0].val.clusterDim = {16, 1, 1};
    cfg.attrs = attrs;
    cfg.numAttrs = 1;
    cudaLaunchKernelEx(&cfg, lstm_rec, (const float*)U, (float*)out);
}

// round 14
// speedup vs baseline: 1.8006x; 1.5251x over previous
#include <cuda_runtime.h>
#include <math.h>

// Problem constants
constexpr int BB = 64;     // batch
constexpr int SS = 2048;   // seq len
constexpr int II = 256;    // input dim
constexpr int HH = 512;    // hidden dim
constexpr int GG = 1536;   // 3*H

// ---------------- device scratch (no allocations allowed) ----------------
__device__ float g_xproj[(size_t)BB * SS * GG];  // precomputed input projections
__device__ float g_hA[BB * HH];                  // h ping
__device__ float g_hB[BB * HH];                  // h pong
__device__ unsigned g_gcnt[4];   // per-group arrival counter (self-resetting)
__device__ unsigned g_ggen[4];   // per-group step counter: gen = latest published h step
__device__ unsigned g_done[4];   // end-of-kernel reset counter

// ---------------- acquire/release helpers ----------------
__device__ __forceinline__ unsigned ld_acq(const unsigned* p) {
    unsigned v;
    asm volatile("ld.acquire.gpu.global.u32 %0, [%1];" : "=r"(v) : "l"(p) : "memory");
    return v;
}
__device__ __forceinline__ void st_rel(unsigned* p, unsigned v) {
    asm volatile("st.release.gpu.global.u32 [%0], %1;" :: "l"(p), "r"(v) : "memory");
}
__device__ __forceinline__ void named_bar(int id, int cnt) {
    asm volatile("bar.sync %0, %1;" :: "r"(id), "r"(cnt) : "memory");
}

// ---------------- f32x2 helpers (FFMA2 — only reachable via PTX) ----------------
__device__ __forceinline__ void ffma2(unsigned long long& d,
                                      unsigned long long a,
                                      unsigned long long b) {
    asm("fma.rn.f32x2 %0, %1, %2, %0;" : "+l"(d) : "l"(a), "l"(b));
}
__device__ __forceinline__ unsigned long long dup2(float x) {
    unsigned long long r;
    asm("mov.b64 %0, {%1, %1};" : "=l"(r) : "f"(x));
    return r;
}
__device__ __forceinline__ float2 unpack2(unsigned long long v) {
    float2 f;
    asm("mov.b64 {%0, %1}, %2;" : "=f"(f.x), "=f"(f.y) : "l"(v));
    return f;
}

// Fast, NaN-safe sigmoid/tanh (MUFU-based; error << 1e-3 tolerance)
__device__ __forceinline__ float fsigmoid(float z) {
    return __fdividef(1.f, 1.f + __expf(-z));
}
__device__ __forceinline__ float ftanh(float x) {
    return fmaf(2.f, fsigmoid(2.f * x), -1.f);
}

// ---------------- Phase 1: x_proj = x @ W + bias ----------------
// (unchanged — known good, ~1.7 ms, near SIMT fp32 roofline)
__global__ __launch_bounds__(256) void gemm_xw(const float* __restrict__ A,
                                               const float* __restrict__ Bm,
                                               const float* __restrict__ bias) {
    __shared__ float As[16 * 132];
    __shared__ float Bs[16 * 132];
    const int tid = threadIdx.x;
    const int bx = blockIdx.x;
    const int by = blockIdx.y;
    const int tr = tid >> 4, tc = tid & 15;
    const int rowA0 = by * 128;
    const int colB0 = bx * 128;
    const int iA_r = tid >> 2;
    const int iA_c = (tid & 3) * 4;
    const int iB_r = tid >> 5;
    const int iB_c = (tid & 31) * 4;

    unsigned long long acc2[8][4];
#pragma unroll
    for (int i = 0; i < 8; i++)
#pragma unroll
        for (int j = 0; j < 4; j++) acc2[i][j] = 0ull;

    for (int kt = 0; kt < II; kt += 16) {
#pragma unroll
        for (int off = 0; off < 128; off += 64) {
            float4 v = *(const float4*)&A[(size_t)(rowA0 + iA_r + off) * II + kt + iA_c];
            As[(iA_c + 0) * 132 + iA_r + off] = v.x;
            As[(iA_c + 1) * 132 + iA_r + off] = v.y;
            As[(iA_c + 2) * 132 + iA_r + off] = v.z;
            As[(iA_c + 3) * 132 + iA_r + off] = v.w;
        }
#pragma unroll
        for (int off = 0; off < 16; off += 8) {
            float4 v = *(const float4*)&Bm[(size_t)(kt + iB_r + off) * GG + colB0 + iB_c];
            *(float4*)&Bs[(iB_r + off) * 132 + iB_c] = v;
        }
        __syncthreads();
#pragma unroll
        for (int k = 0; k < 16; k++) {
            float rm[8];
            *(float4*)&rm[0] = *(const float4*)&As[k * 132 + tr * 8];
            *(float4*)&rm[4] = *(const float4*)&As[k * 132 + tr * 8 + 4];
            unsigned long long bb[4];
#pragma unroll
            for (int jp = 0; jp < 4; jp++)
                bb[jp] = *(const unsigned long long*)&Bs[k * 132 + 32 * jp + 2 * tc];
#pragma unroll
            for (int i = 0; i < 8; i++) {
                unsigned long long a = dup2(rm[i]);
#pragma unroll
                for (int j = 0; j < 4; j++) ffma2(acc2[i][j], a, bb[j]);
            }
        }
        __syncthreads();
    }
#pragma unroll
    for (int i = 0; i < 8; i++) {
        int row = rowA0 + tr * 8 + i;
#pragma unroll
        for (int jp = 0; jp < 4; jp++) {
            int col = colB0 + 32 * jp + 2 * tc;
            float2 bv = *(const float2*)&bias[col];
            float2 p = unpack2(acc2[i][jp]);
            float2 o;
            o.x = p.x + bv.x;
            o.y = p.y + bv.y;
            *(float2*)&g_xproj[(size_t)row * GG + col] = o;
        }
    }
}

// ---------------- Phase 2: persistent recurrence kernel ----------------
// 128 CTAs = 4 batch-groups(16 rows) x 32 feature-groups(16 features).
// 16 warps, k-split 32 each, every warp covers the full 16x48 tile.
// Warp-autonomous restart: each warp polls gen>=t, loads its OWN 16x32 h
// slice into private smem, syncwarp, matmul. One __syncthreads per step.
constexpr int NT  = 512;
constexpr int PU  = 1028;            // U2 pair pitch; 6*PU ≡ 24 (mod 32) -> cgi quads {0,24,16,8}
constexpr int PHW = 36;              // per-warp h pitch; mult-of-4 (16B align) + banks 4rgi
constexpr int SM_U2 = 24 * PU;       // 24,672 floats
constexpr int SM_H  = 16 * (16 * PHW);  // 9,216 floats (16 warps x 16x32 slice +pad)
constexpr int SM_RED = 16 * 768;     // 12,288 floats
constexpr int SMEM_BYTES = (SM_U2 + SM_H + SM_RED) * 4;  // 184,704 B

__global__ __launch_bounds__(NT, 1) void lstm_rec(const float* __restrict__ U,
                                                  float* __restrict__ out) {
    extern __shared__ float sm[];
    float* U2_s = sm;                       // [pair][2k+par], pitch PU
    float* h_s  = sm + SM_U2;               // per-warp regions of 16 x PHW
    float* red  = sm + SM_U2 + SM_H;        // [w][r][col48]

    const int tid = threadIdx.x;
    const int bid = blockIdx.x;
    const int mg = bid >> 5;                // batch group 0..3
    const int ng = bid & 31;                // feature group 0..31
    const int r0 = mg * 16;
    const int n16 = ng * 16;

    // Load U slice pair-interleaved: local col c=2jp+par -> global gate*512+n16+(c&15)
    for (int idx = tid; idx < 24 * 512; idx += NT) {
        int jp = idx % 24;
        int k = idx / 24;
        int c0 = 2 * jp, c1 = 2 * jp + 1;
        int colg0 = (c0 >> 4) * HH + n16 + (c0 & 15);
        int colg1 = (c1 >> 4) * HH + n16 + (c1 & 15);
        U2_s[jp * PU + 2 * k]     = U[(size_t)k * GG + colg0];
        U2_s[jp * PU + 2 * k + 1] = U[(size_t)k * GG + colg1];
    }

    const int lane = tid & 31, w = tid >> 5;  // 16 warps, k-chunk 32 each
    const int rgi = lane & 7;                 // rows rgi, rgi+8
    const int cgi = lane >> 3;                // pairs 6cgi..6cgi+5
    float* hreg = h_s + w * (16 * PHW);       // this warp's private h slice
    const int kg = 32 * w;                    // global k base
    const int ldr = lane >> 1, ldh = lane & 1;  // h loader mapping

    // Elementwise mapping: threads 0..255 own (er, ef)
    const int er = tid >> 4, ef = tid & 15;
    const bool do_elem = (tid < 256);

    float* outh = out + (size_t)BB * SS * HH;
    float* outc = outh + BB * HH;
    unsigned* genp = &g_ggen[mg];

    __syncthreads();  // U2_s ready

    for (int t = 0; t < SS; ++t) {
        // ---- warp-autonomous wait: h(t) published? ----
        if (t > 0) {
            if (lane == 0) {
                while (ld_acq(genp) < (unsigned)t) { }
            }
            __syncwarp();
        }

        // xp prefetch (DRAM latency hidden behind h load + matmul)
        float xp[3];
        if (do_elem) {
#pragma unroll
            for (int g2 = 0; g2 < 3; g2++)
                xp[g2] = __ldg(&g_xproj[((size_t)(r0 + er) * SS + t) * GG + g2 * HH + n16 + ef]);
        }

        // ---- load this warp's own 16x32 h slice (no block sync needed) ----
        if (t == 0) {
            for (int i = lane; i < 16 * PHW; i += 32) hreg[i] = 0.f;
        } else {
            const float* hbuf = (t & 1) ? g_hB : g_hA;
            const float* src = &hbuf[(r0 + ldr) * HH + kg + 16 * ldh];
            float* dst = &hreg[ldr * PHW + 16 * ldh];   // PHW mult of 4 -> 16B aligned
#pragma unroll
            for (int q = 0; q < 4; q++) {
                float4 v = __ldcg((const float4*)(src + 4 * q));
                *(float4*)(dst + 4 * q) = v;
            }
        }
        __syncwarp();

        // ---- matmul: 16 rows x 48 cols over own 32-deep k chunk ----
        unsigned long long acc2[2][6];
#pragma unroll
        for (int i = 0; i < 2; i++)
#pragma unroll
            for (int j = 0; j < 6; j++) acc2[i][j] = 0ull;

#pragma unroll 4
        for (int kk = 0; kk < 32; kk += 2) {
            float2 h0 = *(const float2*)&hreg[rgi * PHW + kk];
            float2 h1 = *(const float2*)&hreg[(rgi + 8) * PHW + kk];
            unsigned long long a00 = dup2(h0.x), a01 = dup2(h0.y);
            unsigned long long a10 = dup2(h1.x), a11 = dup2(h1.y);
#pragma unroll
            for (int jj = 0; jj < 6; jj++) {
                ulonglong2 ub = *(const ulonglong2*)&U2_s[(6 * cgi + jj) * PU + 2 * (kg + kk)];
                ffma2(acc2[0][jj], a00, ub.x);
                ffma2(acc2[0][jj], a01, ub.y);
                ffma2(acc2[1][jj], a10, ub.x);
                ffma2(acc2[1][jj], a11, ub.y);
            }
        }

        // ---- store partials ----
#pragma unroll
        for (int i = 0; i < 2; i++) {
            int r = rgi + 8 * i;
#pragma unroll
            for (int jj = 0; jj < 6; jj++) {
                float2 fv = unpack2(acc2[i][jj]);
                *(float2*)&red[w * 768 + r * 48 + 12 * cgi + 2 * jj] = fv;
            }
        }
        __syncthreads();    // sole block-wide sync of the step

        // ---- fused 16-way reduce + elementwise (threads 0..255) ----
        if (do_elem) {
            float gate[3];
#pragma unroll
            for (int g2 = 0; g2 < 3; g2++) {
                int o = er * 48 + g2 * 16 + ef;
                float s0 = red[0 * 768 + o] + red[1 * 768 + o];
                float s1 = red[2 * 768 + o] + red[3 * 768 + o];
                float s2 = red[4 * 768 + o] + red[5 * 768 + o];
                float s3 = red[6 * 768 + o] + red[7 * 768 + o];
                float s4 = red[8 * 768 + o] + red[9 * 768 + o];
                float s5 = red[10 * 768 + o] + red[11 * 768 + o];
                float s6 = red[12 * 768 + o] + red[13 * 768 + o];
                float s7 = red[14 * 768 + o] + red[15 * 768 + o];
                gate[g2] = xp[g2] + (((s0 + s1) + (s2 + s3)) + ((s4 + s5) + (s6 + s7)));
            }
            float iv = fsigmoid(gate[0]);
            float gv = ftanh(gate[1]);
            float ov = fsigmoid(gate[2]);
            float cv = iv * gv;                  // no-forget: c = i*g
            float hv = ov * ftanh(cv);
            int b = r0 + er, jg = n16 + ef;

            if (t < SS - 1) {
                float* hnext = ((t + 1) & 1) ? g_hB : g_hA;
                __stcg(&hnext[b * HH + jg], hv);     // publish h(t+1)
            } else {
                outh[b * HH + jg] = hv;              // h_f
                outc[b * HH + jg] = cv;              // c_f
            }
            named_bar(9, 256);                       // elem warps' h stores done
            if (tid == 0 && t < SS - 1) {
                __threadfence();
                if (atomicAdd(&g_gcnt[mg], 1u) == 31u) {
                    g_gcnt[mg] = 0;
                    st_rel(genp, (unsigned)(t + 1));  // release: h(t+1) + reset visible
                }
            }
            out[((size_t)b * SS + t) * HH + jg] = hv;  // hidden_seq (off critical path)
        }
    }

    // ---- replay hygiene: last CTA of group resets gen (all polls are done) ----
    if (tid == 0) {
        if (atomicAdd(&g_done[mg], 1u) == 31u) {
            g_done[mg] = 0;
            st_rel(genp, 0u);
        }
    }
}

// ---------------- launch ----------------
extern "C" void kernel_launch(void* const* d_in, const int* in_sizes, int n_in,
                              void* d_out, int out_size) {
    const float* x    = (const float*)d_in[0];
    const float* W    = (const float*)d_in[1];
    const float* U    = (const float*)d_in[2];
    const float* bias = (const float*)d_in[3];
    float* out = (float*)d_out;

    cudaFuncSetAttribute(lstm_rec, cudaFuncAttributeMaxDynamicSharedMemorySize, SMEM_BYTES);

    dim3 g1(GG / 128, (BB * SS) / 128);   // 12 x 1024
    gemm_xw<<<g1, 256>>>(x, W, bias);
    lstm_rec<<<128, NT, SMEM_BYTES>>>(U, out);
}

// round 15
// speedup vs baseline: 1.8070x; 1.0036x over previous
#include <cuda_runtime.h>
#include <math.h>

// Problem constants
constexpr int BB = 64;     // batch
constexpr int SS = 2048;   // seq len
constexpr int II = 256;    // input dim
constexpr int HH = 512;    // hidden dim
constexpr int GG = 1536;   // 3*H

// ---------------- device scratch (no allocations allowed) ----------------
__device__ float g_xproj[(size_t)BB * SS * GG];  // precomputed input projections
__device__ float g_hA[BB * HH];                  // h ping
__device__ float g_hB[BB * HH];                  // h pong
__device__ unsigned g_gcnt[4];   // per-group arrival counter (self-resetting)
__device__ unsigned g_ggen[4];   // per-group step counter: gen = latest published h step
__device__ unsigned g_done[4];   // end-of-kernel reset counter

// ---------------- acquire/release helpers ----------------
__device__ __forceinline__ unsigned ld_acq(const unsigned* p) {
    unsigned v;
    asm volatile("ld.acquire.gpu.global.u32 %0, [%1];" : "=r"(v) : "l"(p) : "memory");
    return v;
}
__device__ __forceinline__ void st_rel(unsigned* p, unsigned v) {
    asm volatile("st.release.gpu.global.u32 [%0], %1;" :: "l"(p), "r"(v) : "memory");
}
__device__ __forceinline__ void named_bar(int id, int cnt) {
    asm volatile("bar.sync %0, %1;" :: "r"(id), "r"(cnt) : "memory");
}

// ---------------- f32x2 helpers (FFMA2 — only reachable via PTX) ----------------
__device__ __forceinline__ void ffma2(unsigned long long& d,
                                      unsigned long long a,
                                      unsigned long long b) {
    asm("fma.rn.f32x2 %0, %1, %2, %0;" : "+l"(d) : "l"(a), "l"(b));
}
__device__ __forceinline__ unsigned long long dup2(float x) {
    unsigned long long r;
    asm("mov.b64 %0, {%1, %1};" : "=l"(r) : "f"(x));
    return r;
}
__device__ __forceinline__ float2 unpack2(unsigned long long v) {
    float2 f;
    asm("mov.b64 {%0, %1}, %2;" : "=f"(f.x), "=f"(f.y) : "l"(v));
    return f;
}

// Fast, NaN-safe sigmoid/tanh (MUFU-based; error << 1e-3 tolerance)
__device__ __forceinline__ float fsigmoid(float z) {
    return __fdividef(1.f, 1.f + __expf(-z));
}
__device__ __forceinline__ float ftanh(float x) {
    return fmaf(2.f, fsigmoid(2.f * x), -1.f);
}

// ---------------- Phase 1: x_proj = x @ W + bias ----------------
// (unchanged — known good, ~1.7 ms, near SIMT fp32 roofline)
__global__ __launch_bounds__(256) void gemm_xw(const float* __restrict__ A,
                                               const float* __restrict__ Bm,
                                               const float* __restrict__ bias) {
    __shared__ float As[16 * 132];
    __shared__ float Bs[16 * 132];
    const int tid = threadIdx.x;
    const int bx = blockIdx.x;
    const int by = blockIdx.y;
    const int tr = tid >> 4, tc = tid & 15;
    const int rowA0 = by * 128;
    const int colB0 = bx * 128;
    const int iA_r = tid >> 2;
    const int iA_c = (tid & 3) * 4;
    const int iB_r = tid >> 5;
    const int iB_c = (tid & 31) * 4;

    unsigned long long acc2[8][4];
#pragma unroll
    for (int i = 0; i < 8; i++)
#pragma unroll
        for (int j = 0; j < 4; j++) acc2[i][j] = 0ull;

    for (int kt = 0; kt < II; kt += 16) {
#pragma unroll
        for (int off = 0; off < 128; off += 64) {
            float4 v = *(const float4*)&A[(size_t)(rowA0 + iA_r + off) * II + kt + iA_c];
            As[(iA_c + 0) * 132 + iA_r + off] = v.x;
            As[(iA_c + 1) * 132 + iA_r + off] = v.y;
            As[(iA_c + 2) * 132 + iA_r + off] = v.z;
            As[(iA_c + 3) * 132 + iA_r + off] = v.w;
        }
#pragma unroll
        for (int off = 0; off < 16; off += 8) {
            float4 v = *(const float4*)&Bm[(size_t)(kt + iB_r + off) * GG + colB0 + iB_c];
            *(float4*)&Bs[(iB_r + off) * 132 + iB_c] = v;
        }
        __syncthreads();
#pragma unroll
        for (int k = 0; k < 16; k++) {
            float rm[8];
            *(float4*)&rm[0] = *(const float4*)&As[k * 132 + tr * 8];
            *(float4*)&rm[4] = *(const float4*)&As[k * 132 + tr * 8 + 4];
            unsigned long long bb[4];
#pragma unroll
            for (int jp = 0; jp < 4; jp++)
                bb[jp] = *(const unsigned long long*)&Bs[k * 132 + 32 * jp + 2 * tc];
#pragma unroll
            for (int i = 0; i < 8; i++) {
                unsigned long long a = dup2(rm[i]);
#pragma unroll
                for (int j = 0; j < 4; j++) ffma2(acc2[i][j], a, bb[j]);
            }
        }
        __syncthreads();
    }
#pragma unroll
    for (int i = 0; i < 8; i++) {
        int row = rowA0 + tr * 8 + i;
#pragma unroll
        for (int jp = 0; jp < 4; jp++) {
            int col = colB0 + 32 * jp + 2 * tc;
            float2 bv = *(const float2*)&bias[col];
            float2 p = unpack2(acc2[i][jp]);
            float2 o;
            o.x = p.x + bv.x;
            o.y = p.y + bv.y;
            *(float2*)&g_xproj[(size_t)row * GG + col] = o;
        }
    }
}

// ---------------- Phase 2: persistent recurrence kernel ----------------
// 128 CTAs = 4 batch-groups(16 rows) x 32 feature-groups(16 features).
// 16 warps, k-split 32 each. ONE L2 poller per CTA (warp 15) publishes the
// observed step to a smem flag; other warps spin on smem (no L2 traffic),
// then restart autonomously: own h slice -> syncwarp -> matmul.
constexpr int NT  = 512;
constexpr int PU  = 1028;            // U2 pair pitch; 6*PU ≡ 24 (mod 32) -> cgi quads {0,24,16,8}
constexpr int PHW = 36;              // per-warp h pitch; mult-of-4 (16B align) + banks 4rgi
constexpr int SM_U2 = 24 * PU;       // 24,672 floats
constexpr int SM_H  = 16 * (16 * PHW);  // 9,216 floats (16 warps x 16x32 slice +pad)
constexpr int SM_RED = 16 * 768;     // 12,288 floats
constexpr int SMEM_BYTES = (SM_U2 + SM_H + SM_RED) * 4;  // 184,704 B

__global__ __launch_bounds__(NT, 1) void lstm_rec(const float* __restrict__ U,
                                                  float* __restrict__ out) {
    extern __shared__ float sm[];
    float* U2_s = sm;                       // [pair][2k+par], pitch PU
    float* h_s  = sm + SM_U2;               // per-warp regions of 16 x PHW
    float* red  = sm + SM_U2 + SM_H;        // [w][r][col48]
    __shared__ unsigned s_flag;             // latest step observed in g_ggen[mg]

    const int tid = threadIdx.x;
    const int bid = blockIdx.x;
    const int mg = bid >> 5;                // batch group 0..3
    const int ng = bid & 31;                // feature group 0..31
    const int r0 = mg * 16;
    const int n16 = ng * 16;

    if (tid == 0) s_flag = 0u;

    // Load U slice pair-interleaved: local col c=2jp+par -> global gate*512+n16+(c&15)
    for (int idx = tid; idx < 24 * 512; idx += NT) {
        int jp = idx % 24;
        int k = idx / 24;
        int c0 = 2 * jp, c1 = 2 * jp + 1;
        int colg0 = (c0 >> 4) * HH + n16 + (c0 & 15);
        int colg1 = (c1 >> 4) * HH + n16 + (c1 & 15);
        U2_s[jp * PU + 2 * k]     = U[(size_t)k * GG + colg0];
        U2_s[jp * PU + 2 * k + 1] = U[(size_t)k * GG + colg1];
    }

    const int lane = tid & 31, w = tid >> 5;  // 16 warps, k-chunk 32 each
    const int rgi = lane & 7;                 // rows rgi, rgi+8
    const int cgi = lane >> 3;                // pairs 6cgi..6cgi+5
    float* hreg = h_s + w * (16 * PHW);       // this warp's private h slice
    const int kg = 32 * w;                    // global k base
    const int ldr = lane >> 1, ldh = lane & 1;  // h loader mapping

    // Elementwise mapping: threads 0..255 own (er, ef)
    const int er = tid >> 4, ef = tid & 15;
    const bool do_elem = (tid < 256);

    float* outh = out + (size_t)BB * SS * HH;
    float* outc = outh + BB * HH;
    unsigned* genp = &g_ggen[mg];
    volatile unsigned* sfp = &s_flag;

    __syncthreads();  // U2_s + s_flag ready

    for (int t = 0; t < SS; ++t) {
        // ---- hierarchical wait: warp 15 polls L2 once per CTA, others spin on smem ----
        if (t > 0) {
            if (w == 15) {
                if (lane == 0) {
                    while (ld_acq(genp) < (unsigned)t) { }
                    *sfp = (unsigned)t;          // STS: local broadcast
                }
            } else {
                if (lane == 0) {
                    while (*sfp < (unsigned)t) { }   // LDS spin: no L2 traffic
                }
            }
            __syncwarp();
        }

        // xp prefetch (DRAM latency hidden behind h load + matmul)
        float xp[3];
        if (do_elem) {
#pragma unroll
            for (int g2 = 0; g2 < 3; g2++)
                xp[g2] = __ldg(&g_xproj[((size_t)(r0 + er) * SS + t) * GG + g2 * HH + n16 + ef]);
        }

        // ---- load this warp's own 16x32 h slice (no block sync needed) ----
        if (t == 0) {
            for (int i = lane; i < 16 * PHW; i += 32) hreg[i] = 0.f;
        } else {
            const float* hbuf = (t & 1) ? g_hB : g_hA;
            const float* src = &hbuf[(r0 + ldr) * HH + kg + 16 * ldh];
            float* dst = &hreg[ldr * PHW + 16 * ldh];   // PHW mult of 4 -> 16B aligned
#pragma unroll
            for (int q = 0; q < 4; q++) {
                float4 v = __ldcg((const float4*)(src + 4 * q));
                *(float4*)(dst + 4 * q) = v;
            }
        }
        __syncwarp();

        // ---- matmul: 16 rows x 48 cols over own 32-deep k chunk ----
        unsigned long long acc2[2][6];
#pragma unroll
        for (int i = 0; i < 2; i++)
#pragma unroll
            for (int j = 0; j < 6; j++) acc2[i][j] = 0ull;

#pragma unroll 4
        for (int kk = 0; kk < 32; kk += 2) {
            float2 h0 = *(const float2*)&hreg[rgi * PHW + kk];
            float2 h1 = *(const float2*)&hreg[(rgi + 8) * PHW + kk];
            unsigned long long a00 = dup2(h0.x), a01 = dup2(h0.y);
            unsigned long long a10 = dup2(h1.x), a11 = dup2(h1.y);
#pragma unroll
            for (int jj = 0; jj < 6; jj++) {
                ulonglong2 ub = *(const ulonglong2*)&U2_s[(6 * cgi + jj) * PU + 2 * (kg + kk)];
                ffma2(acc2[0][jj], a00, ub.x);
                ffma2(acc2[0][jj], a01, ub.y);
                ffma2(acc2[1][jj], a10, ub.x);
                ffma2(acc2[1][jj], a11, ub.y);
            }
        }

        // ---- store partials ----
#pragma unroll
        for (int i = 0; i < 2; i++) {
            int r = rgi + 8 * i;
#pragma unroll
            for (int jj = 0; jj < 6; jj++) {
                float2 fv = unpack2(acc2[i][jj]);
                *(float2*)&red[w * 768 + r * 48 + 12 * cgi + 2 * jj] = fv;
            }
        }
        __syncthreads();    // sole block-wide sync of the step

        // ---- fused 16-way reduce + elementwise (threads 0..255) ----
        if (do_elem) {
            float gate[3];
#pragma unroll
            for (int g2 = 0; g2 < 3; g2++) {
                int o = er * 48 + g2 * 16 + ef;
                float s0 = red[0 * 768 + o] + red[1 * 768 + o];
                float s1 = red[2 * 768 + o] + red[3 * 768 + o];
                float s2 = red[4 * 768 + o] + red[5 * 768 + o];
                float s3 = red[6 * 768 + o] + red[7 * 768 + o];
                float s4 = red[8 * 768 + o] + red[9 * 768 + o];
                float s5 = red[10 * 768 + o] + red[11 * 768 + o];
                float s6 = red[12 * 768 + o] + red[13 * 768 + o];
                float s7 = red[14 * 768 + o] + red[15 * 768 + o];
                gate[g2] = xp[g2] + (((s0 + s1) + (s2 + s3)) + ((s4 + s5) + (s6 + s7)));
            }
            float iv = fsigmoid(gate[0]);
            float gv = ftanh(gate[1]);
            float ov = fsigmoid(gate[2]);
            float cv = iv * gv;                  // no-forget: c = i*g
            float hv = ov * ftanh(cv);
            int b = r0 + er, jg = n16 + ef;

            if (t < SS - 1) {
                float* hnext = ((t + 1) & 1) ? g_hB : g_hA;
                __stcg(&hnext[b * HH + jg], hv);     // publish h(t+1)
            } else {
                outh[b * HH + jg] = hv;              // h_f
                outc[b * HH + jg] = cv;              // c_f
            }
            named_bar(9, 256);                       // elem warps' h stores done
            if (tid == 0 && t < SS - 1) {
                __threadfence();
                if (atomicAdd(&g_gcnt[mg], 1u) == 31u) {
                    g_gcnt[mg] = 0;
                    st_rel(genp, (unsigned)(t + 1));  // release: h(t+1) + reset visible
                }
            }
            out[((size_t)b * SS + t) * HH + jg] = hv;  // hidden_seq (off critical path)
        }
    }

    // ---- replay hygiene: last CTA of group resets gen (all polls are done) ----
    if (tid == 0) {
        if (atomicAdd(&g_done[mg], 1u) == 31u) {
            g_done[mg] = 0;
            st_rel(genp, 0u);
        }
    }
}

// ---------------- launch ----------------
extern "C" void kernel_launch(void* const* d_in, const int* in_sizes, int n_in,
                              void* d_out, int out_size) {
    const float* x    = (const float*)d_in[0];
    const float* W    = (const float*)d_in[1];
    const float* U    = (const float*)d_in[2];
    const float* bias = (const float*)d_in[3];
    float* out = (float*)d_out;

    cudaFuncSetAttribute(lstm_rec, cudaFuncAttributeMaxDynamicSharedMemorySize, SMEM_BYTES);

    dim3 g1(GG / 128, (BB * SS) / 128);   // 12 x 1024
    gemm_xw<<<g1, 256>>>(x, W, bias);
    lstm_rec<<<128, NT, SMEM_BYTES>>>(U, out);
}

// round 16
// speedup vs baseline: 1.9524x; 1.0805x over previous
#include <cuda_runtime.h>
#include <math.h>

// Problem constants
constexpr int BB = 64;     // batch
constexpr int SS = 2048;   // seq len
constexpr int II = 256;    // input dim
constexpr int HH = 512;    // hidden dim
constexpr int GG = 1536;   // 3*H

// ---------------- device scratch (no allocations allowed) ----------------
__device__ float g_xproj[(size_t)BB * SS * GG];  // precomputed input projections
__device__ float g_h[8][BB * HH];                // 8-deep h ring (slot t&7 = h(t); slot0 zeros)
__device__ unsigned g_flagp[4][32][32];          // per-CTA step flags, PADDED: one 128B line each
__device__ unsigned g_gcnt[4];                   // skew-bound barrier counter (self-resetting)
__device__ unsigned g_ggen[4];                   // skew-bound barrier generation (monotonic)

// ---------------- acquire/release helpers ----------------
__device__ __forceinline__ unsigned ld_acq(const unsigned* p) {
    unsigned v;
    asm volatile("ld.acquire.gpu.global.u32 %0, [%1];" : "=r"(v) : "l"(p) : "memory");
    return v;
}
__device__ __forceinline__ void st_rel(unsigned* p, unsigned v) {
    asm volatile("st.release.gpu.global.u32 [%0], %1;" :: "l"(p), "r"(v) : "memory");
}
__device__ __forceinline__ void named_bar(int id, int cnt) {
    asm volatile("bar.sync %0, %1;" :: "r"(id), "r"(cnt) : "memory");
}

// ---------------- f32x2 helpers (FFMA2 — only reachable via PTX) ----------------
__device__ __forceinline__ void ffma2(unsigned long long& d,
                                      unsigned long long a,
                                      unsigned long long b) {
    asm("fma.rn.f32x2 %0, %1, %2, %0;" : "+l"(d) : "l"(a), "l"(b));
}
__device__ __forceinline__ unsigned long long dup2(float x) {
    unsigned long long r;
    asm("mov.b64 %0, {%1, %1};" : "=l"(r) : "f"(x));
    return r;
}
__device__ __forceinline__ float2 unpack2(unsigned long long v) {
    float2 f;
    asm("mov.b64 {%0, %1}, %2;" : "=f"(f.x), "=f"(f.y) : "l"(v));
    return f;
}

// Fast, NaN-safe sigmoid/tanh (MUFU-based; error << 1e-3 tolerance)
__device__ __forceinline__ float fsigmoid(float z) {
    return __fdividef(1.f, 1.f + __expf(-z));
}
__device__ __forceinline__ float ftanh(float x) {
    return fmaf(2.f, fsigmoid(2.f * x), -1.f);
}

// ---------------- Phase 1: x_proj = x @ W + bias ----------------
// (unchanged — known good, ~1.7 ms)
__global__ __launch_bounds__(256) void gemm_xw(const float* __restrict__ A,
                                               const float* __restrict__ Bm,
                                               const float* __restrict__ bias) {
    __shared__ float As[16 * 132];
    __shared__ float Bs[16 * 132];
    const int tid = threadIdx.x;
    const int bx = blockIdx.x;
    const int by = blockIdx.y;
    const int tr = tid >> 4, tc = tid & 15;
    const int rowA0 = by * 128;
    const int colB0 = bx * 128;
    const int iA_r = tid >> 2;
    const int iA_c = (tid & 3) * 4;
    const int iB_r = tid >> 5;
    const int iB_c = (tid & 31) * 4;

    unsigned long long acc2[8][4];
#pragma unroll
    for (int i = 0; i < 8; i++)
#pragma unroll
        for (int j = 0; j < 4; j++) acc2[i][j] = 0ull;

    for (int kt = 0; kt < II; kt += 16) {
#pragma unroll
        for (int off = 0; off < 128; off += 64) {
            float4 v = *(const float4*)&A[(size_t)(rowA0 + iA_r + off) * II + kt + iA_c];
            As[(iA_c + 0) * 132 + iA_r + off] = v.x;
            As[(iA_c + 1) * 132 + iA_r + off] = v.y;
            As[(iA_c + 2) * 132 + iA_r + off] = v.z;
            As[(iA_c + 3) * 132 + iA_r + off] = v.w;
        }
#pragma unroll
        for (int off = 0; off < 16; off += 8) {
            float4 v = *(const float4*)&Bm[(size_t)(kt + iB_r + off) * GG + colB0 + iB_c];
            *(float4*)&Bs[(iB_r + off) * 132 + iB_c] = v;
        }
        __syncthreads();
#pragma unroll
        for (int k = 0; k < 16; k++) {
            float rm[8];
            *(float4*)&rm[0] = *(const float4*)&As[k * 132 + tr * 8];
            *(float4*)&rm[4] = *(const float4*)&As[k * 132 + tr * 8 + 4];
            unsigned long long bb[4];
#pragma unroll
            for (int jp = 0; jp < 4; jp++)
                bb[jp] = *(const unsigned long long*)&Bs[k * 132 + 32 * jp + 2 * tc];
#pragma unroll
            for (int i = 0; i < 8; i++) {
                unsigned long long a = dup2(rm[i]);
#pragma unroll
                for (int j = 0; j < 4; j++) ffma2(acc2[i][j], a, bb[j]);
            }
        }
        __syncthreads();
    }
#pragma unroll
    for (int i = 0; i < 8; i++) {
        int row = rowA0 + tr * 8 + i;
#pragma unroll
        for (int jp = 0; jp < 4; jp++) {
            int col = colB0 + 32 * jp + 2 * tc;
            float2 bv = *(const float2*)&bias[col];
            float2 p = unpack2(acc2[i][jp]);
            float2 o;
            o.x = p.x + bv.x;
            o.y = p.y + bv.y;
            *(float2*)&g_xproj[(size_t)row * GG + col] = o;
        }
    }
}

// ---------------- skew-bound group barrier (every 7 steps only) ----------------
__device__ __forceinline__ void groupbar(int mg) {
    __syncthreads();
    if (threadIdx.x == 0) {
        __threadfence();
        unsigned gen = ld_acq(&g_ggen[mg]);
        if (atomicAdd(&g_gcnt[mg], 1u) == 31u) {
            g_gcnt[mg] = 0;
            st_rel(&g_ggen[mg], gen + 1);
        } else {
            while (ld_acq(&g_ggen[mg]) == gen) { }
        }
    }
    __syncthreads();
}

// ---------------- Phase 2: persistent recurrence kernel ----------------
// 128 CTAs = 4 batch-groups(16 rows) x 32 feature-groups(16 features).
// 16 warps, k-split 32 each. POINT-TO-POINT dataflow: warp w consumes only
// feature-groups 2w,2w+1 -> polls exactly 2 per-CTA flags (each on its own
// 128B line, <=32 pollers/line). Producer publishes its own flag; no atomics,
// no all-to-all max. 8-deep h ring + groupbar every 7 steps bounds skew.
constexpr int NT  = 512;
constexpr int PU  = 1028;            // U2 pair pitch; cgi quads conflict-free
constexpr int PHW = 36;              // per-warp h pitch; 16B-aligned float4s
constexpr int SM_U2 = 24 * PU;       // 24,672 floats
constexpr int SM_H  = 16 * (16 * PHW);  // 9,216 floats
constexpr int SM_RED = 16 * 768;     // 12,288 floats
constexpr int SMEM_BYTES = (SM_U2 + SM_H + SM_RED) * 4;  // 184,704 B

__global__ __launch_bounds__(NT, 1) void lstm_rec(const float* __restrict__ U,
                                                  float* __restrict__ out) {
    extern __shared__ float sm[];
    float* U2_s = sm;                       // [pair][2k+par], pitch PU
    float* h_s  = sm + SM_U2;               // per-warp regions of 16 x PHW
    float* red  = sm + SM_U2 + SM_H;        // [w][r][col48]

    const int tid = threadIdx.x;
    const int bid = blockIdx.x;
    const int mg = bid >> 5;                // batch group 0..3
    const int ng = bid & 31;                // feature group 0..31
    const int r0 = mg * 16;
    const int n16 = ng * 16;

    // Load U slice pair-interleaved
    for (int idx = tid; idx < 24 * 512; idx += NT) {
        int jp = idx % 24;
        int k = idx / 24;
        int c0 = 2 * jp, c1 = 2 * jp + 1;
        int colg0 = (c0 >> 4) * HH + n16 + (c0 & 15);
        int colg1 = (c1 >> 4) * HH + n16 + (c1 & 15);
        U2_s[jp * PU + 2 * k]     = U[(size_t)k * GG + colg0];
        U2_s[jp * PU + 2 * k + 1] = U[(size_t)k * GG + colg1];
    }

    const int lane = tid & 31, w = tid >> 5;  // 16 warps, k-chunk 32 each
    const int rgi = lane & 7;                 // rows rgi, rgi+8
    const int cgi = lane >> 3;                // pairs 6cgi..6cgi+5
    float* hreg = h_s + w * (16 * PHW);       // this warp's private h slice
    const int kg = 32 * w;                    // global k base
    const int ldr = lane >> 1, ldh = lane & 1;  // h loader mapping

    // Elementwise mapping: threads 0..255 own (er, ef)
    const int er = tid >> 4, ef = tid & 15;
    const bool do_elem = (tid < 256);

    float* outh = out + (size_t)BB * SS * HH;
    float* outc = outh + BB * HH;
    unsigned* myflag = &g_flagp[mg][ng][0];
    // warp w's two producer flags (feature groups 2w, 2w+1); lanes 0,1 poll in parallel
    const unsigned* pflag = &g_flagp[mg][2 * w + (lane & 1)][0];

    __syncthreads();  // U2_s ready

    for (int t = 0; t < SS; ++t) {
        // ---- point-to-point wait: only this warp's 2 producers ----
        if (t > 0) {
            if (lane < 2) {
                while (ld_acq(pflag) < (unsigned)t) { }
            }
            __syncwarp();
        }

        // xp prefetch (DRAM latency hidden behind h load + matmul)
        float xp[3];
        if (do_elem) {
#pragma unroll
            for (int g2 = 0; g2 < 3; g2++)
                xp[g2] = __ldg(&g_xproj[((size_t)(r0 + er) * SS + t) * GG + g2 * HH + n16 + ef]);
        }

        // ---- load this warp's own 16x32 h slice from ring slot t&7 ----
        if (t == 0) {
            for (int i = lane; i < 16 * PHW; i += 32) hreg[i] = 0.f;
        } else {
            const float* hbuf = g_h[t & 7];
            const float* src = &hbuf[(r0 + ldr) * HH + kg + 16 * ldh];
            float* dst = &hreg[ldr * PHW + 16 * ldh];   // PHW mult of 4 -> 16B aligned
#pragma unroll
            for (int q = 0; q < 4; q++) {
                float4 v = __ldcg((const float4*)(src + 4 * q));
                *(float4*)(dst + 4 * q) = v;
            }
        }
        __syncwarp();

        // ---- matmul: 16 rows x 48 cols over own 32-deep k chunk ----
        unsigned long long acc2[2][6];
#pragma unroll
        for (int i = 0; i < 2; i++)
#pragma unroll
            for (int j = 0; j < 6; j++) acc2[i][j] = 0ull;

#pragma unroll 4
        for (int kk = 0; kk < 32; kk += 2) {
            float2 h0 = *(const float2*)&hreg[rgi * PHW + kk];
            float2 h1 = *(const float2*)&hreg[(rgi + 8) * PHW + kk];
            unsigned long long a00 = dup2(h0.x), a01 = dup2(h0.y);
            unsigned long long a10 = dup2(h1.x), a11 = dup2(h1.y);
#pragma unroll
            for (int jj = 0; jj < 6; jj++) {
                ulonglong2 ub = *(const ulonglong2*)&U2_s[(6 * cgi + jj) * PU + 2 * (kg + kk)];
                ffma2(acc2[0][jj], a00, ub.x);
                ffma2(acc2[0][jj], a01, ub.y);
                ffma2(acc2[1][jj], a10, ub.x);
                ffma2(acc2[1][jj], a11, ub.y);
            }
        }

        // ---- store partials ----
#pragma unroll
        for (int i = 0; i < 2; i++) {
            int r = rgi + 8 * i;
#pragma unroll
            for (int jj = 0; jj < 6; jj++) {
                float2 fv = unpack2(acc2[i][jj]);
                *(float2*)&red[w * 768 + r * 48 + 12 * cgi + 2 * jj] = fv;
            }
        }
        __syncthreads();    // sole block-wide sync of the step

        // ---- fused 16-way reduce + elementwise (threads 0..255) ----
        if (do_elem) {
            float gate[3];
#pragma unroll
            for (int g2 = 0; g2 < 3; g2++) {
                int o = er * 48 + g2 * 16 + ef;
                float s0 = red[0 * 768 + o] + red[1 * 768 + o];
                float s1 = red[2 * 768 + o] + red[3 * 768 + o];
                float s2 = red[4 * 768 + o] + red[5 * 768 + o];
                float s3 = red[6 * 768 + o] + red[7 * 768 + o];
                float s4 = red[8 * 768 + o] + red[9 * 768 + o];
                float s5 = red[10 * 768 + o] + red[11 * 768 + o];
                float s6 = red[12 * 768 + o] + red[13 * 768 + o];
                float s7 = red[14 * 768 + o] + red[15 * 768 + o];
                gate[g2] = xp[g2] + (((s0 + s1) + (s2 + s3)) + ((s4 + s5) + (s6 + s7)));
            }
            float iv = fsigmoid(gate[0]);
            float gv = ftanh(gate[1]);
            float ov = fsigmoid(gate[2]);
            float cv = iv * gv;                  // no-forget: c = i*g
            float hv = ov * ftanh(cv);
            int b = r0 + er, jg = n16 + ef;

            if (t < SS - 1) {
                __stcg(&g_h[(t + 1) & 7][b * HH + jg], hv);   // publish h(t+1)
            } else {
                outh[b * HH + jg] = hv;              // h_f
                outc[b * HH + jg] = cv;              // c_f
            }
            named_bar(9, 256);                       // this CTA's h stores done
            if (tid == 0 && t < SS - 1) {
                __threadfence();
                st_rel(myflag, (unsigned)(t + 1));   // own flag: no atomics, no funnel
            }
            out[((size_t)b * SS + t) * HH + jg] = hv;  // hidden_seq (off critical path)
        }

        // skew bound for 8-deep ring: barrier every 7 steps
        if ((t % 7 == 6) && t < SS - 1) groupbar(mg);
    }

    // ---- replay hygiene: after all polls in group are done, reset own flag ----
    groupbar(mg);
    if (tid == 0) st_rel(myflag, 0u);
}

// ---------------- launch ----------------
extern "C" void kernel_launch(void* const* d_in, const int* in_sizes, int n_in,
                              void* d_out, int out_size) {
    const float* x    = (const float*)d_in[0];
    const float* W    = (const float*)d_in[1];
    const float* U    = (const float*)d_in[2];
    const float* bias = (const float*)d_in[3];
    float* out = (float*)d_out;

    cudaFuncSetAttribute(lstm_rec, cudaFuncAttributeMaxDynamicSharedMemorySize, SMEM_BYTES);

    dim3 g1(GG / 128, (BB * SS) / 128);   // 12 x 1024
    gemm_xw<<<g1, 256>>>(x, W, bias);
    lstm_rec<<<128, NT, SMEM_BYTES>>>(U, out);
}

// round 17
// speedup vs baseline: 2.0887x; 1.0698x over previous
#include <cuda_runtime.h>
#include <math.h>

// Problem constants
constexpr int BB = 64;     // batch
constexpr int SS = 2048;   // seq len
constexpr int II = 256;    // input dim
constexpr int HH = 512;    // hidden dim
constexpr int GG = 1536;   // 3*H

// ---------------- device scratch (no allocations allowed) ----------------
__device__ float g_xproj[(size_t)BB * SS * GG];  // precomputed input projections
__device__ float g_h[8][BB * HH];                // 8-deep h ring (slot t&7 = h(t); slot0 zeros)
__device__ unsigned g_flagp[4][32][32];          // per-CTA step flags, PADDED: one 128B line each
__device__ unsigned g_gcnt[4];                   // skew-bound barrier counter (self-resetting)
__device__ unsigned g_ggen[4];                   // skew-bound barrier generation (monotonic)

// ---------------- acquire/release helpers ----------------
__device__ __forceinline__ unsigned ld_acq(const unsigned* p) {
    unsigned v;
    asm volatile("ld.acquire.gpu.global.u32 %0, [%1];" : "=r"(v) : "l"(p) : "memory");
    return v;
}
__device__ __forceinline__ void st_rel(unsigned* p, unsigned v) {
    asm volatile("st.release.gpu.global.u32 [%0], %1;" :: "l"(p), "r"(v) : "memory");
}
__device__ __forceinline__ void named_bar(int id, int cnt) {
    asm volatile("bar.sync %0, %1;" :: "r"(id), "r"(cnt) : "memory");
}

// ---------------- f32x2 helpers (FFMA2 — only reachable via PTX) ----------------
__device__ __forceinline__ void ffma2(unsigned long long& d,
                                      unsigned long long a,
                                      unsigned long long b) {
    asm("fma.rn.f32x2 %0, %1, %2, %0;" : "+l"(d) : "l"(a), "l"(b));
}
__device__ __forceinline__ unsigned long long dup2(float x) {
    unsigned long long r;
    asm("mov.b64 %0, {%1, %1};" : "=l"(r) : "f"(x));
    return r;
}
__device__ __forceinline__ float2 unpack2(unsigned long long v) {
    float2 f;
    asm("mov.b64 {%0, %1}, %2;" : "=f"(f.x), "=f"(f.y) : "l"(v));
    return f;
}

// Fast, NaN-safe sigmoid/tanh (MUFU-based; error << 1e-3 tolerance)
__device__ __forceinline__ float fsigmoid(float z) {
    return __fdividef(1.f, 1.f + __expf(-z));
}
__device__ __forceinline__ float ftanh(float x) {
    return fmaf(2.f, fsigmoid(2.f * x), -1.f);
}

// ---------------- Phase 1: x_proj = x @ W + bias ----------------
// (unchanged — known good, ~1.7 ms)
__global__ __launch_bounds__(256) void gemm_xw(const float* __restrict__ A,
                                               const float* __restrict__ Bm,
                                               const float* __restrict__ bias) {
    __shared__ float As[16 * 132];
    __shared__ float Bs[16 * 132];
    const int tid = threadIdx.x;
    const int bx = blockIdx.x;
    const int by = blockIdx.y;
    const int tr = tid >> 4, tc = tid & 15;
    const int rowA0 = by * 128;
    const int colB0 = bx * 128;
    const int iA_r = tid >> 2;
    const int iA_c = (tid & 3) * 4;
    const int iB_r = tid >> 5;
    const int iB_c = (tid & 31) * 4;

    unsigned long long acc2[8][4];
#pragma unroll
    for (int i = 0; i < 8; i++)
#pragma unroll
        for (int j = 0; j < 4; j++) acc2[i][j] = 0ull;

    for (int kt = 0; kt < II; kt += 16) {
#pragma unroll
        for (int off = 0; off < 128; off += 64) {
            float4 v = *(const float4*)&A[(size_t)(rowA0 + iA_r + off) * II + kt + iA_c];
            As[(iA_c + 0) * 132 + iA_r + off] = v.x;
            As[(iA_c + 1) * 132 + iA_r + off] = v.y;
            As[(iA_c + 2) * 132 + iA_r + off] = v.z;
            As[(iA_c + 3) * 132 + iA_r + off] = v.w;
        }
#pragma unroll
        for (int off = 0; off < 16; off += 8) {
            float4 v = *(const float4*)&Bm[(size_t)(kt + iB_r + off) * GG + colB0 + iB_c];
            *(float4*)&Bs[(iB_r + off) * 132 + iB_c] = v;
        }
        __syncthreads();
#pragma unroll
        for (int k = 0; k < 16; k++) {
            float rm[8];
            *(float4*)&rm[0] = *(const float4*)&As[k * 132 + tr * 8];
            *(float4*)&rm[4] = *(const float4*)&As[k * 132 + tr * 8 + 4];
            unsigned long long bb[4];
#pragma unroll
            for (int jp = 0; jp < 4; jp++)
                bb[jp] = *(const unsigned long long*)&Bs[k * 132 + 32 * jp + 2 * tc];
#pragma unroll
            for (int i = 0; i < 8; i++) {
                unsigned long long a = dup2(rm[i]);
#pragma unroll
                for (int j = 0; j < 4; j++) ffma2(acc2[i][j], a, bb[j]);
            }
        }
        __syncthreads();
    }
#pragma unroll
    for (int i = 0; i < 8; i++) {
        int row = rowA0 + tr * 8 + i;
#pragma unroll
        for (int jp = 0; jp < 4; jp++) {
            int col = colB0 + 32 * jp + 2 * tc;
            float2 bv = *(const float2*)&bias[col];
            float2 p = unpack2(acc2[i][jp]);
            float2 o;
            o.x = p.x + bv.x;
            o.y = p.y + bv.y;
            *(float2*)&g_xproj[(size_t)row * GG + col] = o;
        }
    }
}

// ---------------- skew-bound group barrier (every 7 steps only) ----------------
__device__ __forceinline__ void groupbar(int mg) {
    __syncthreads();
    if (threadIdx.x == 0) {
        __threadfence();
        unsigned gen = ld_acq(&g_ggen[mg]);
        if (atomicAdd(&g_gcnt[mg], 1u) == 31u) {
            g_gcnt[mg] = 0;
            st_rel(&g_ggen[mg], gen + 1);
        } else {
            while (ld_acq(&g_ggen[mg]) == gen) { }
        }
    }
    __syncthreads();
}

// ---------------- Phase 2: persistent recurrence kernel ----------------
// 128 CTAs = 4 batch-groups(16 rows) x 32 feature-groups(16 features).
// 16 warps, k-split 32 each. Lane tile 4 rows x 6 cols (was 2x12): each U
// LDS.128 feeds 4 rows -> crossbar bytes/step drop 7168->5120 cyc (L1 was
// the binding pipe at 57%). Point-to-point producer flags (R16, proven).
constexpr int NT  = 512;
constexpr int PU  = 1028;            // U2 pair pitch; cgi banks 12cgi mod 32 distinct
constexpr int PHW = 36;              // per-warp h pitch; 16B-aligned float4s
constexpr int SM_U2 = 24 * PU;       // 24,672 floats
constexpr int SM_H  = 16 * (16 * PHW);  // 9,216 floats
constexpr int SM_RED = 16 * 768;     // 12,288 floats
constexpr int SMEM_BYTES = (SM_U2 + SM_H + SM_RED) * 4;  // 184,704 B

__global__ __launch_bounds__(NT, 1) void lstm_rec(const float* __restrict__ U,
                                                  float* __restrict__ out) {
    extern __shared__ float sm[];
    float* U2_s = sm;                       // [pair][2k+par], pitch PU
    float* h_s  = sm + SM_U2;               // per-warp regions of 16 x PHW
    float* red  = sm + SM_U2 + SM_H;        // [w][r][col48]

    const int tid = threadIdx.x;
    const int bid = blockIdx.x;
    const int mg = bid >> 5;                // batch group 0..3
    const int ng = bid & 31;                // feature group 0..31
    const int r0 = mg * 16;
    const int n16 = ng * 16;

    // Load U slice pair-interleaved
    for (int idx = tid; idx < 24 * 512; idx += NT) {
        int jp = idx % 24;
        int k = idx / 24;
        int c0 = 2 * jp, c1 = 2 * jp + 1;
        int colg0 = (c0 >> 4) * HH + n16 + (c0 & 15);
        int colg1 = (c1 >> 4) * HH + n16 + (c1 & 15);
        U2_s[jp * PU + 2 * k]     = U[(size_t)k * GG + colg0];
        U2_s[jp * PU + 2 * k + 1] = U[(size_t)k * GG + colg1];
    }

    const int lane = tid & 31, w = tid >> 5;  // 16 warps, k-chunk 32 each
    const int rgi = lane & 3;                 // row group: rows rgi+4i, i=0..3
    const int cgi = lane >> 2;                // col group 0..7: pairs 3cgi..3cgi+2
    float* hreg = h_s + w * (16 * PHW);       // this warp's private h slice
    const int kg = 32 * w;                    // global k base
    const int ldr = lane >> 1, ldh = lane & 1;  // h loader mapping

    // Elementwise mapping: threads 0..255 own (er, ef)
    const int er = tid >> 4, ef = tid & 15;
    const bool do_elem = (tid < 256);

    float* outh = out + (size_t)BB * SS * HH;
    float* outc = outh + BB * HH;
    unsigned* myflag = &g_flagp[mg][ng][0];
    // warp w's two producer flags (feature groups 2w, 2w+1); lanes 0,1 poll in parallel
    const unsigned* pflag = &g_flagp[mg][2 * w + (lane & 1)][0];

    __syncthreads();  // U2_s ready

    for (int t = 0; t < SS; ++t) {
        // ---- point-to-point wait: only this warp's 2 producers ----
        if (t > 0) {
            if (lane < 2) {
                while (ld_acq(pflag) < (unsigned)t) { }
            }
            __syncwarp();
        }

        // xp prefetch (DRAM latency hidden behind h load + matmul)
        float xp[3];
        if (do_elem) {
#pragma unroll
            for (int g2 = 0; g2 < 3; g2++)
                xp[g2] = __ldg(&g_xproj[((size_t)(r0 + er) * SS + t) * GG + g2 * HH + n16 + ef]);
        }

        // ---- load this warp's own 16x32 h slice from ring slot t&7 ----
        if (t == 0) {
            for (int i = lane; i < 16 * PHW; i += 32) hreg[i] = 0.f;
        } else {
            const float* hbuf = g_h[t & 7];
            const float* src = &hbuf[(r0 + ldr) * HH + kg + 16 * ldh];
            float* dst = &hreg[ldr * PHW + 16 * ldh];   // PHW mult of 4 -> 16B aligned
#pragma unroll
            for (int q = 0; q < 4; q++) {
                float4 v = __ldcg((const float4*)(src + 4 * q));
                *(float4*)(dst + 4 * q) = v;
            }
        }
        __syncwarp();

        // ---- matmul: lane tile 4 rows x 3 pairs over own 32-deep k chunk ----
        unsigned long long acc2[4][3];
#pragma unroll
        for (int i = 0; i < 4; i++)
#pragma unroll
            for (int j = 0; j < 3; j++) acc2[i][j] = 0ull;

#pragma unroll 4
        for (int kk = 0; kk < 32; kk += 2) {
            // 4 h rows (rgi+4i): each LDS.64 has 4 distinct addrs (8-way bcast),
            // banks {4rgi+16i+kk} distinct within instruction -> conflict-free
            float2 h2[4];
#pragma unroll
            for (int i = 0; i < 4; i++)
                h2[i] = *(const float2*)&hreg[(rgi + 4 * i) * PHW + kk];
            unsigned long long a0[4], a1[4];
#pragma unroll
            for (int i = 0; i < 4; i++) {
                a0[i] = dup2(h2[i].x);
                a1[i] = dup2(h2[i].y);
            }
#pragma unroll
            for (int jj = 0; jj < 3; jj++) {
                ulonglong2 ub = *(const ulonglong2*)&U2_s[(3 * cgi + jj) * PU + 2 * (kg + kk)];
#pragma unroll
                for (int i = 0; i < 4; i++) {
                    ffma2(acc2[i][jj], a0[i], ub.x);
                    ffma2(acc2[i][jj], a1[i], ub.y);
                }
            }
        }

        // ---- store partials: lane rows rgi+4i, col-pairs 3cgi+jj ----
#pragma unroll
        for (int i = 0; i < 4; i++) {
            int r = rgi + 4 * i;
#pragma unroll
            for (int jj = 0; jj < 3; jj++) {
                float2 fv = unpack2(acc2[i][jj]);
                *(float2*)&red[w * 768 + r * 48 + 6 * cgi + 2 * jj] = fv;
            }
        }
        __syncthreads();    // sole block-wide sync of the step

        // ---- fused 16-way reduce + elementwise (threads 0..255) ----
        if (do_elem) {
            float gate[3];
#pragma unroll
            for (int g2 = 0; g2 < 3; g2++) {
                int o = er * 48 + g2 * 16 + ef;
                float s0 = red[0 * 768 + o] + red[1 * 768 + o];
                float s1 = red[2 * 768 + o] + red[3 * 768 + o];
                float s2 = red[4 * 768 + o] + red[5 * 768 + o];
                float s3 = red[6 * 768 + o] + red[7 * 768 + o];
                float s4 = red[8 * 768 + o] + red[9 * 768 + o];
                float s5 = red[10 * 768 + o] + red[11 * 768 + o];
                float s6 = red[12 * 768 + o] + red[13 * 768 + o];
                float s7 = red[14 * 768 + o] + red[15 * 768 + o];
                gate[g2] = xp[g2] + (((s0 + s1) + (s2 + s3)) + ((s4 + s5) + (s6 + s7)));
            }
            float iv = fsigmoid(gate[0]);
            float gv = ftanh(gate[1]);
            float ov = fsigmoid(gate[2]);
            float cv = iv * gv;                  // no-forget: c = i*g
            float hv = ov * ftanh(cv);
            int b = r0 + er, jg = n16 + ef;

            if (t < SS - 1) {
                __stcg(&g_h[(t + 1) & 7][b * HH + jg], hv);   // publish h(t+1)
            } else {
                outh[b * HH + jg] = hv;              // h_f
                outc[b * HH + jg] = cv;              // c_f
            }
            named_bar(9, 256);                       // this CTA's h stores done
            if (tid == 0 && t < SS - 1) {
                __threadfence();
                st_rel(myflag, (unsigned)(t + 1));   // own flag: no atomics, no funnel
            }
            out[((size_t)b * SS + t) * HH + jg] = hv;  // hidden_seq (off critical path)
        }

        // skew bound for 8-deep ring: barrier every 7 steps
        if ((t % 7 == 6) && t < SS - 1) groupbar(mg);
    }

    // ---- replay hygiene: after all polls in group are done, reset own flag ----
    groupbar(mg);
    if (tid == 0) st_rel(myflag, 0u);
}

// ---------------- launch ----------------
extern "C" void kernel_launch(void* const* d_in, const int* in_sizes, int n_in,
                              void* d_out, int out_size) {
    const float* x    = (const float*)d_in[0];
    const float* W    = (const float*)d_in[1];
    const float* U    = (const float*)d_in[2];
    const float* bias = (const float*)d_in[3];
    float* out = (float*)d_out;

    cudaFuncSetAttribute(lstm_rec, cudaFuncAttributeMaxDynamicSharedMemorySize, SMEM_BYTES);

    dim3 g1(GG / 128, (BB * SS) / 128);   // 12 x 1024
    gemm_xw<<<g1, 256>>>(x, W, bias);
    lstm_rec<<<128, NT, SMEM_BYTES>>>(U, out);
}